// round 13
// baseline (speedup 1.0000x reference)
#include <cuda_runtime.h>

typedef unsigned long long ull;

#define NB 32
#define ND 256
#define NN 8192
#define NPART 2
#define CHPP (ND / NPART)      // 128 channels per part
#define CNT_PER_CH (NB * NN)   // 262144

// ---------------- scratch (static device globals; no runtime alloc) ----------
__device__ float  g_six[NPART * NB * 6 * NN];  // partials of the 6-ch conv
__device__ float  g_x2 [NB * 2 * NN];
__device__ float  g_r  [NB * NN];
__device__ float  g_y3 [NB * 2 * NN];
__device__ double g_bn1[4];
__device__ double g_bn2[4];

// ---------------- f32x2 helpers ----------------------------------------------
__device__ __forceinline__ ull pack2(float lo, float hi) {
    ull r; asm("mov.b64 %0, {%1,%2};" : "=l"(r) : "f"(lo), "f"(hi)); return r;
}
__device__ __forceinline__ void unpack2(ull v, float& lo, float& hi) {
    asm("mov.b64 {%0,%1}, %2;" : "=f"(lo), "=f"(hi) : "l"(v));
}
__device__ __forceinline__ ull fma2(ull a, ull b, ull c) {
    ull d; asm("fma.rn.f32x2 %0, %1, %2, %3;" : "=l"(d) : "l"(a), "l"(b), "l"(c));
    return d;
}

// ---------------- fast BN constants (fp64 only for mean/var products) --------
__device__ __forceinline__ void bn_consts(const double* acc,
                                          const float* g, const float* beta,
                                          float* cs)
{
    const double ic = 1.0 / (double)CNT_PER_CH;
    double m0d = acc[0] * ic;
    double v0d = acc[1] * ic - m0d * m0d;
    double m1d = acc[2] * ic;
    double v1d = acc[3] * ic - m1d * m1d;
    float v0 = (float)v0d + 1e-5f;
    float v1 = (float)v1d + 1e-5f;
    float m0 = (float)m0d, m1 = (float)m1d;
    float i0 = rsqrtf(v0); i0 *= (1.5f - 0.5f * v0 * i0 * i0);
    float i1 = rsqrtf(v1); i1 *= (1.5f - 0.5f * v1 * i1 * i1);
    float s0 = g[0] * i0, s1 = g[1] * i1;
    cs[0] = s0; cs[1] = beta[0] - m0 * s0;
    cs[2] = s1; cs[3] = beta[1] - m1 * s1;
}

// ---------------- block reduction --------------------------------------------
__device__ __forceinline__ float brsum(float v) {
    __shared__ float sb[8];
    #pragma unroll
    for (int o = 16; o; o >>= 1) v += __shfl_down_sync(0xffffffffu, v, o);
    if ((threadIdx.x & 31) == 0) sb[threadIdx.x >> 5] = v;
    __syncthreads();
    if (threadIdx.x < 32) {
        v = (threadIdx.x < 8) ? sb[threadIdx.x] : 0.f;
        #pragma unroll
        for (int o = 4; o; o >>= 1) v += __shfl_down_sync(0xffffffffu, v, o);
    }
    __syncthreads();
    return v;  // valid on thread 0
}

// ---------------- K1: heavy conv, f32x2, unroll-8 MLP ------------------------
// grid (16, 2, 32): x = n-tile of 512, y = channel half, z = batch.
// 128 threads; 4 points/thread; plain in-loop loads + unroll 8 (ptxas
// front-batches the 8 LDG.128s per window -> ~2x bytes-in-flight vs unroll 4;
// manual register buffers regressed twice, so the compiler owns the batching).
// (128,6): reg cap 85, body ~76 -> no spill; 24 warps/SM.
__global__ __launch_bounds__(128, 6) void k1_conv(
    const float* __restrict__ feats,
    const float* __restrict__ rot_w,  const float* __restrict__ rot_b,
    const float* __restrict__ trans_w, const float* __restrict__ trans_b)
{
    // per il row of 18 ulls (144B, 16B-aligned):
    //   slots 0..11:  [W0_o, W1_o] pairs for o = 0..5
    //   slots 12..17: [W2_0,W2_1][W2_2,W2_3][W2_4,W2_5]
    __shared__ __align__(16) ull ws[CHPP * 18];
    const int tid  = threadIdx.x;
    const int w    = tid >> 5;
    const int l    = tid & 31;
    const int part = blockIdx.y;
    const int b    = blockIdx.z;

    // fused zero of BN1 accumulators (consumed in k3, after k2's atomics)
    if (blockIdx.x == 0 && part == 0 && b == 0 && tid < 4) g_bn1[tid] = 0.0;

    for (int idx = tid; idx < CHPP * 18; idx += 128) {
        int ich = idx / 18, rem = idx % 18;
        int o, k;
        if (rem < 12) { o = rem >> 1; k = rem & 1; }
        else          { o = rem - 12; k = 2; }
        int i = part * CHPP + ich;
        float wv = (o < 4) ? rot_w[o * 768 + i * 3 + k]
                           : trans_w[(o - 4) * 768 + i * 3 + k];
        ws[idx] = pack2(wv, wv);
    }
    __syncthreads();

    const int warp_n0 = blockIdx.x * 512 + w * 128;   // warp's first point
    const int n0      = warp_n0 + l * 4;
    const float* fbase = feats + ((size_t)(b * ND + part * CHPP)) * NN + n0;
    const bool wl = (warp_n0 > 0);           // warp-left halo exists
    const bool wr_ok = (warp_n0 + 128 < NN); // warp-right halo exists

    ull acc[6][2];
    #pragma unroll
    for (int o = 0; o < 6; ++o) { acc[o][0] = 0ULL; acc[o][1] = 0ULL; }

    #pragma unroll 8
    for (int il = 0; il < CHPP; ++il) {
        const float* fp = fbase + (size_t)il * NN;
        float4 v = *(const float4*)fp;

        // halos from neighbor lanes (exact same values as loads would give)
        float lf = __shfl_up_sync(0xffffffffu, v.w, 1);
        float rf = __shfl_down_sync(0xffffffffu, v.x, 1);
        if (l == 0)  lf = wl    ? fp[-1] : 0.f;   // 1-lane predicated LDG
        if (l == 31) rf = wr_ok ? fp[4]  : 0.f;   // 1-lane predicated LDG

        ull d0 = pack2(lf,  v.x), d1 = pack2(v.x, v.y), d2 = pack2(v.y, v.z),
            d3 = pack2(v.z, v.w), d4 = pack2(v.w, rf);
        const ull* wr = ws + il * 18;

        #pragma unroll
        for (int j = 0; j < 3; ++j) {          // channel pairs (2j, 2j+1)
            ulonglong2 w01a = *(const ulonglong2*)(wr + 4 * j);      // o=2j
            ulonglong2 w01b = *(const ulonglong2*)(wr + 4 * j + 2);  // o=2j+1
            ulonglong2 w2p  = *(const ulonglong2*)(wr + 12 + 2 * j); // W2 pair

            acc[2*j][0]   = fma2(d0, w01a.x, acc[2*j][0]);
            acc[2*j][0]   = fma2(d1, w01a.y, acc[2*j][0]);
            acc[2*j][0]   = fma2(d2, w2p.x,  acc[2*j][0]);
            acc[2*j][1]   = fma2(d2, w01a.x, acc[2*j][1]);
            acc[2*j][1]   = fma2(d3, w01a.y, acc[2*j][1]);
            acc[2*j][1]   = fma2(d4, w2p.x,  acc[2*j][1]);

            acc[2*j+1][0] = fma2(d0, w01b.x, acc[2*j+1][0]);
            acc[2*j+1][0] = fma2(d1, w01b.y, acc[2*j+1][0]);
            acc[2*j+1][0] = fma2(d2, w2p.y,  acc[2*j+1][0]);
            acc[2*j+1][1] = fma2(d2, w01b.x, acc[2*j+1][1]);
            acc[2*j+1][1] = fma2(d3, w01b.y, acc[2*j+1][1]);
            acc[2*j+1][1] = fma2(d4, w2p.y,  acc[2*j+1][1]);
        }
    }

    #pragma unroll
    for (int o = 0; o < 6; ++o) {
        // bias contributed exactly once (the parts are summed in K2)
        float bias = (part == 0) ? ((o < 4) ? rot_b[o] : trans_b[o - 4]) : 0.f;
        float p0, p1, p2, p3;
        unpack2(acc[o][0], p0, p1);
        unpack2(acc[o][1], p2, p3);
        float* dst = g_six + ((size_t)((part * NB + b) * 6 + o)) * NN + n0;
        *(float4*)dst = make_float4(p0 + bias, p1 + bias, p2 + bias, p3 + bias);
    }
}

// ---------------- K2: offsets + pos conv (precontracted) + ratio + BN1 sums --
// grid (8, 32): x = n-tile of 1024, y = batch. 256 threads, 4 pts/thread.
__global__ __launch_bounds__(256) void k2_pos(
    const float* __restrict__ pts,
    const float* __restrict__ pos_w, const float* __restrict__ pos_b)
{
    __shared__ float sc[6][9];   // [c*3+k][ap0,ap1,aa,ab,ac,ad,atx,aty,kappa]
    __shared__ float pw[120];
    __shared__ float pbs[2];
    const int tid = threadIdx.x;

    // fused zero of BN2 accumulators (consumed in k4, after k3's atomics)
    if (blockIdx.x == 0 && blockIdx.y == 0 && tid >= 32 && tid < 36)
        g_bn2[tid - 32] = 0.0;

    if (tid < 120) pw[tid] = pos_w[tid];
    if (tid < 2)   pbs[tid] = pos_b[tid];
    __syncthreads();

    const float R0c[9] = {-1.f,-1.f,-1.f, 0.f,0.f,0.f, 1.f,1.f,1.f};
    const float R1c[9] = {-1.f, 0.f, 1.f,-1.f,0.f,1.f,-1.f,0.f,1.f};

    if (tid < 6) {
        int c = tid / 3, k = tid % 3;
        float aa = 0.f, ab = 0.f, ac = 0.f, ad = 0.f, atx = 0.f, aty = 0.f;
        #pragma unroll
        for (int r = 0; r < 9; ++r) {
            float wox = pw[c * 60 + (2 + 2 * r) * 3 + k];
            float woy = pw[c * 60 + (3 + 2 * r) * 3 + k];
            aa += wox * R0c[r]; ab += wox * R1c[r]; atx += wox;
            ac += woy * R0c[r]; ad += woy * R1c[r]; aty += woy;
        }
        sc[tid][0] = pw[c * 60 + 0 + k];
        sc[tid][1] = pw[c * 60 + 3 + k];
        sc[tid][2] = aa; sc[tid][3] = ab; sc[tid][4] = ac; sc[tid][5] = ad;
        sc[tid][6] = atx; sc[tid][7] = aty;
        sc[tid][8] = -(aa + ad);           // kappa
    }
    __syncthreads();

    const int b  = blockIdx.y;
    const int n0 = blockIdx.x * 1024 + tid * 4;
    const bool has_l = (n0 > 0);
    const bool has_r = (n0 + 4 < NN);

    // load 6 summed channels (2 parts) + 2 pts over window 0..5 (= n0-1..n0+4)
    float va[6], vb[6], vc[6], vd[6], vtx[6], vty[6], vp0[6], vp1[6];
    {
        #pragma unroll
        for (int ch = 0; ch < 6; ++ch) {
            float l = 0.f, r = 0.f;
            float4 s4 = make_float4(0.f, 0.f, 0.f, 0.f);
            #pragma unroll
            for (int p = 0; p < NPART; ++p) {
                const float* s = g_six + ((size_t)((p * NB + b) * 6 + ch)) * NN + n0;
                float4 a = *(const float4*)s;
                s4.x += a.x; s4.y += a.y; s4.z += a.z; s4.w += a.w;
                if (has_l) l += s[-1];
                if (has_r) r += s[4];
            }
            float* dst = (ch == 0) ? va : (ch == 1) ? vb : (ch == 2) ? vc
                       : (ch == 3) ? vd : (ch == 4) ? vtx : vty;
            dst[0] = l; dst[1] = s4.x; dst[2] = s4.y;
            dst[3] = s4.z; dst[4] = s4.w; dst[5] = r;
        }
        const float* p0p = pts + (size_t)(b * 2 + 0) * NN + n0;
        const float* p1p = pts + (size_t)(b * 2 + 1) * NN + n0;
        float4 q0 = *(const float4*)p0p;
        float4 q1 = *(const float4*)p1p;
        vp0[0] = has_l ? p0p[-1] : 0.f;  vp1[0] = has_l ? p1p[-1] : 0.f;
        vp0[5] = has_r ? p0p[4]  : 0.f;  vp1[5] = has_r ? p1p[4]  : 0.f;
        vp0[1] = q0.x; vp0[2] = q0.y; vp0[3] = q0.z; vp0[4] = q0.w;
        vp1[1] = q1.x; vp1[2] = q1.y; vp1[3] = q1.z; vp1[4] = q1.w;
    }

    float x2a[4], x2b[4], rmax[4];
    #pragma unroll
    for (int j = 0; j < 4; ++j) { x2a[j] = pbs[0]; x2b[j] = pbs[1]; }

    #pragma unroll
    for (int t = 0; t < 6; ++t) {
        int nn = n0 - 1 + t;
        if (nn < 0 || nn >= NN) continue;   // zero-padded conv input
        #pragma unroll
        for (int ck = 0; ck < 6; ++ck) {
            float s = sc[ck][8];
            s += sc[ck][0] * vp0[t] + sc[ck][1] * vp1[t];
            s += sc[ck][2] * va[t]  + sc[ck][3] * vb[t];
            s += sc[ck][4] * vc[t]  + sc[ck][5] * vd[t];
            s += sc[ck][6] * vtx[t] + sc[ck][7] * vty[t];
            int c = ck / 3, k = ck % 3;
            int j = t - k;
            if (j >= 0 && j < 4) {
                if (c == 0) x2a[j] += s; else x2b[j] += s;
            }
        }
        // center-tap ratio max (position t serves output j = t-1)
        if (t >= 1 && t <= 4) {
            float rm = -3.4e38f;
            #pragma unroll
            for (int r = 0; r < 9; ++r) {
                float ox = va[t] * R0c[r] + vb[t] * R1c[r] - R0c[r] + vtx[t];
                float oy = vc[t] * R0c[r] + vd[t] * R1c[r] - R1c[r] + vty[t];
                float rr = __fdividef(oy + 1e-6f, ox + 1e-6f);
                rm = fmaxf(rm, rr);
            }
            rmax[t - 1] = rm;
        }
    }

    *(float4*)(g_x2 + (size_t)(b * 2 + 0) * NN + n0) = make_float4(x2a[0], x2a[1], x2a[2], x2a[3]);
    *(float4*)(g_x2 + (size_t)(b * 2 + 1) * NN + n0) = make_float4(x2b[0], x2b[1], x2b[2], x2b[3]);
    *(float4*)(g_r + (size_t)b * NN + n0) = make_float4(rmax[0], rmax[1], rmax[2], rmax[3]);

    float sa  = x2a[0] + x2a[1] + x2a[2] + x2a[3];
    float sa2 = x2a[0]*x2a[0] + x2a[1]*x2a[1] + x2a[2]*x2a[2] + x2a[3]*x2a[3];
    float sb2 = x2b[0] + x2b[1] + x2b[2] + x2b[3];
    float sbb = x2b[0]*x2b[0] + x2b[1]*x2b[1] + x2b[2]*x2b[2] + x2b[3]*x2b[3];
    float s;
    s = brsum(sa);  if (tid == 0) atomicAdd(&g_bn1[0], (double)s);
    s = brsum(sa2); if (tid == 0) atomicAdd(&g_bn1[1], (double)s);
    s = brsum(sb2); if (tid == 0) atomicAdd(&g_bn1[2], (double)s);
    s = brsum(sbb); if (tid == 0) atomicAdd(&g_bn1[3], (double)s);
}

// ---------------- K3: BN1 apply + leaky + rotate + ori conv + BN2 sums -------
__global__ __launch_bounds__(256) void k3_ori(
    const float* __restrict__ pos_g, const float* __restrict__ pos_beta,
    const float* __restrict__ ori_w, const float* __restrict__ ori_b)
{
    __shared__ float cs[4];
    __shared__ float ow[12];
    const int tid = threadIdx.x;
    if (tid == 0) bn_consts(g_bn1, pos_g, pos_beta, cs);
    if (tid < 12) ow[tid] = ori_w[tid];
    __syncthreads();

    const float sc0 = cs[0], sh0 = cs[1], sc1 = cs[2], sh1 = cs[3];
    const int b  = blockIdx.y;
    const int n0 = blockIdx.x * 1024 + tid * 4;
    const bool has_l = (n0 > 0);
    const bool has_r = (n0 + 4 < NN);

    float x0v[6], x1v[6], rv[6];
    {
        const float* q0 = g_x2 + (size_t)(b * 2 + 0) * NN + n0;
        const float* q1 = g_x2 + (size_t)(b * 2 + 1) * NN + n0;
        const float* qr = g_r + (size_t)b * NN + n0;
        float4 a0 = *(const float4*)q0;
        float4 a1 = *(const float4*)q1;
        float4 ar = *(const float4*)qr;
        x0v[0] = has_l ? q0[-1] : 0.f;  x1v[0] = has_l ? q1[-1] : 0.f;
        rv[0]  = has_l ? qr[-1] : 0.f;
        x0v[5] = has_r ? q0[4] : 0.f;   x1v[5] = has_r ? q1[4] : 0.f;
        rv[5]  = has_r ? qr[4] : 0.f;
        x0v[1] = a0.x; x0v[2] = a0.y; x0v[3] = a0.z; x0v[4] = a0.w;
        x1v[1] = a1.x; x1v[2] = a1.y; x1v[3] = a1.z; x1v[4] = a1.w;
        rv[1]  = ar.x; rv[2]  = ar.y; rv[3]  = ar.z; rv[4]  = ar.w;
    }

    float o0[4], o1[4];
    #pragma unroll
    for (int j = 0; j < 4; ++j) { o0[j] = ori_b[0]; o1[j] = ori_b[1]; }

    #pragma unroll
    for (int t = 0; t < 6; ++t) {
        int nn = n0 - 1 + t;
        if (nn < 0 || nn >= NN) continue;   // zero-padded conv input

        float r = fminf(fmaxf(rv[t], -1e18f), 1e18f);
        float xb0 = sc0 * x0v[t] + sh0; xb0 = (xb0 >= 0.f) ? xb0 : 0.2f * xb0;
        float xb1 = sc1 * x1v[t] + sh1; xb1 = (xb1 >= 0.f) ? xb1 : 0.2f * xb1;
        float cc = rsqrtf(fmaf(r, r, 1.f));
        float ss = r * cc;
        float y0 = xb0 * cc - xb1 * ss;
        float y1 = xb0 * ss + xb1 * cc;

        #pragma unroll
        for (int k = 0; k < 3; ++k) {
            int j = t - k;
            if (j >= 0 && j < 4) {
                o0[j] += y0 * ow[0 + k] + y1 * ow[3 + k];
                o1[j] += y0 * ow[6 + k] + y1 * ow[9 + k];
            }
        }
    }

    *(float4*)(g_y3 + (size_t)(b * 2 + 0) * NN + n0) = make_float4(o0[0], o0[1], o0[2], o0[3]);
    *(float4*)(g_y3 + (size_t)(b * 2 + 1) * NN + n0) = make_float4(o1[0], o1[1], o1[2], o1[3]);

    float s0  = o0[0] + o0[1] + o0[2] + o0[3];
    float s0q = o0[0]*o0[0] + o0[1]*o0[1] + o0[2]*o0[2] + o0[3]*o0[3];
    float s1  = o1[0] + o1[1] + o1[2] + o1[3];
    float s1q = o1[0]*o1[0] + o1[1]*o1[1] + o1[2]*o1[2] + o1[3]*o1[3];
    float s;
    s = brsum(s0);  if (tid == 0) atomicAdd(&g_bn2[0], (double)s);
    s = brsum(s0q); if (tid == 0) atomicAdd(&g_bn2[1], (double)s);
    s = brsum(s1);  if (tid == 0) atomicAdd(&g_bn2[2], (double)s);
    s = brsum(s1q); if (tid == 0) atomicAdd(&g_bn2[3], (double)s);
}

// ---------------- K4: BN2 apply -> output (float2, 1024 blocks) --------------
__global__ __launch_bounds__(256) void k4_out(
    const float* __restrict__ ori_g, const float* __restrict__ ori_beta,
    float* __restrict__ out)
{
    __shared__ float cs[4];
    const int tid = threadIdx.x;
    if (tid == 0) bn_consts(g_bn2, ori_g, ori_beta, cs);
    __syncthreads();

    int idx = (blockIdx.x * 256 + tid) * 2;
    if (idx >= NB * 2 * NN) return;
    int ch = (idx >> 13) & 1;
    float sc = cs[ch * 2], sh = cs[ch * 2 + 1];
    float2 v = *(const float2*)(g_y3 + idx);
    *(float2*)(out + idx) = make_float2(sc * v.x + sh, sc * v.y + sh);
}

// ---------------- launch ------------------------------------------------------
extern "C" void kernel_launch(void* const* d_in, const int* in_sizes, int n_in,
                              void* d_out, int out_size)
{
    const float* pts      = (const float*)d_in[0];
    const float* feats    = (const float*)d_in[1];
    const float* rot_w    = (const float*)d_in[2];
    const float* rot_b    = (const float*)d_in[3];
    const float* trans_w  = (const float*)d_in[4];
    const float* trans_b  = (const float*)d_in[5];
    const float* pos_w    = (const float*)d_in[6];
    const float* pos_b    = (const float*)d_in[7];
    const float* pos_g    = (const float*)d_in[8];
    const float* pos_beta = (const float*)d_in[9];
    const float* ori_w    = (const float*)d_in[10];
    const float* ori_b    = (const float*)d_in[11];
    const float* ori_g    = (const float*)d_in[12];
    const float* ori_beta = (const float*)d_in[13];
    float* out = (float*)d_out;

    k1_conv<<<dim3(16, NPART, 32), 128>>>(feats, rot_w, rot_b, trans_w, trans_b); // 1
    k2_pos<<<dim3(8, 32), 256>>>(pts, pos_w, pos_b);                              // 2
    k3_ori<<<dim3(8, 32), 256>>>(pos_g, pos_beta, ori_w, ori_b);                  // 3
    k4_out<<<1024, 256>>>(ori_g, ori_beta, out);                                  // 4
}

// round 14
// speedup vs baseline: 1.0688x; 1.0688x over previous
#include <cuda_runtime.h>

typedef unsigned long long ull;

#define NB 32
#define ND 256
#define NN 8192
#define NPART 2
#define CHPP (ND / NPART)      // 128 channels per part
#define CNT_PER_CH (NB * NN)   // 262144

// ---------------- scratch (static device globals; no runtime alloc) ----------
__device__ float  g_six[NPART * NB * 6 * NN];  // partials of the 6-ch conv
__device__ float  g_x2 [NB * 2 * NN];
__device__ float  g_r  [NB * NN];
__device__ float  g_y3 [NB * 2 * NN];
__device__ double g_bn1[4];
__device__ double g_bn2[4];

// ---------------- f32x2 helpers ----------------------------------------------
__device__ __forceinline__ ull pack2(float lo, float hi) {
    ull r; asm("mov.b64 %0, {%1,%2};" : "=l"(r) : "f"(lo), "f"(hi)); return r;
}
__device__ __forceinline__ void unpack2(ull v, float& lo, float& hi) {
    asm("mov.b64 {%0,%1}, %2;" : "=f"(lo), "=f"(hi) : "l"(v));
}
__device__ __forceinline__ ull fma2(ull a, ull b, ull c) {
    ull d; asm("fma.rn.f32x2 %0, %1, %2, %3;" : "=l"(d) : "l"(a), "l"(b), "l"(c));
    return d;
}

// ---------------- fast BN constants (fp64 only for mean/var products) --------
__device__ __forceinline__ void bn_consts(const double* acc,
                                          const float* g, const float* beta,
                                          float* cs)
{
    const double ic = 1.0 / (double)CNT_PER_CH;
    double m0d = acc[0] * ic;
    double v0d = acc[1] * ic - m0d * m0d;
    double m1d = acc[2] * ic;
    double v1d = acc[3] * ic - m1d * m1d;
    float v0 = (float)v0d + 1e-5f;
    float v1 = (float)v1d + 1e-5f;
    float m0 = (float)m0d, m1 = (float)m1d;
    float i0 = rsqrtf(v0); i0 *= (1.5f - 0.5f * v0 * i0 * i0);
    float i1 = rsqrtf(v1); i1 *= (1.5f - 0.5f * v1 * i1 * i1);
    float s0 = g[0] * i0, s1 = g[1] * i1;
    cs[0] = s0; cs[1] = beta[0] - m0 * s0;
    cs[2] = s1; cs[3] = beta[1] - m1 * s1;
}

// ---------------- block reduction --------------------------------------------
__device__ __forceinline__ float brsum(float v) {
    __shared__ float sb[8];
    #pragma unroll
    for (int o = 16; o; o >>= 1) v += __shfl_down_sync(0xffffffffu, v, o);
    if ((threadIdx.x & 31) == 0) sb[threadIdx.x >> 5] = v;
    __syncthreads();
    if (threadIdx.x < 32) {
        v = (threadIdx.x < 8) ? sb[threadIdx.x] : 0.f;
        #pragma unroll
        for (int o = 4; o; o >>= 1) v += __shfl_down_sync(0xffffffffu, v, o);
    }
    __syncthreads();
    return v;  // valid on thread 0
}

// ---------------- K1: heavy conv, f32x2 — round-12 config (best known) -------
// grid (16, 2, 32): x = n-tile of 512, y = channel half, z = batch.
// 128 threads; 4 points/thread; plain in-loop loads + unroll 4 (ptxas batches
// LDGs itself). Halos via SHFL + 1-lane predicated boundary loads.
// (128,8): regs<=64 -> 8 blocks/SM = 32 warps (single fully-resident wave).
__global__ __launch_bounds__(128, 8) void k1_conv(
    const float* __restrict__ feats,
    const float* __restrict__ rot_w,  const float* __restrict__ rot_b,
    const float* __restrict__ trans_w, const float* __restrict__ trans_b)
{
    // per il row of 18 ulls (144B, 16B-aligned):
    //   slots 0..11:  [W0_o, W1_o] pairs for o = 0..5
    //   slots 12..17: [W2_0,W2_1][W2_2,W2_3][W2_4,W2_5]
    __shared__ __align__(16) ull ws[CHPP * 18];
    const int tid  = threadIdx.x;
    const int w    = tid >> 5;
    const int l    = tid & 31;
    const int part = blockIdx.y;
    const int b    = blockIdx.z;

    // fused zero of BN1 accumulators (consumed in k3, after k2's atomics)
    if (blockIdx.x == 0 && part == 0 && b == 0 && tid < 4) g_bn1[tid] = 0.0;

    for (int idx = tid; idx < CHPP * 18; idx += 128) {
        int ich = idx / 18, rem = idx % 18;
        int o, k;
        if (rem < 12) { o = rem >> 1; k = rem & 1; }
        else          { o = rem - 12; k = 2; }
        int i = part * CHPP + ich;
        float wv = (o < 4) ? rot_w[o * 768 + i * 3 + k]
                           : trans_w[(o - 4) * 768 + i * 3 + k];
        ws[idx] = pack2(wv, wv);
    }
    __syncthreads();

    const int warp_n0 = blockIdx.x * 512 + w * 128;   // warp's first point
    const int n0      = warp_n0 + l * 4;
    const float* fbase = feats + ((size_t)(b * ND + part * CHPP)) * NN + n0;
    const bool wl = (warp_n0 > 0);           // warp-left halo exists
    const bool wr_ok = (warp_n0 + 128 < NN); // warp-right halo exists

    ull acc[6][2];
    #pragma unroll
    for (int o = 0; o < 6; ++o) { acc[o][0] = 0ULL; acc[o][1] = 0ULL; }

    #pragma unroll 4
    for (int il = 0; il < CHPP; ++il) {
        const float* fp = fbase + (size_t)il * NN;
        float4 v = *(const float4*)fp;

        // halos from neighbor lanes (exact same values as loads would give)
        float lf = __shfl_up_sync(0xffffffffu, v.w, 1);
        float rf = __shfl_down_sync(0xffffffffu, v.x, 1);
        if (l == 0)  lf = wl    ? fp[-1] : 0.f;   // 1-lane predicated LDG
        if (l == 31) rf = wr_ok ? fp[4]  : 0.f;   // 1-lane predicated LDG

        ull d0 = pack2(lf,  v.x), d1 = pack2(v.x, v.y), d2 = pack2(v.y, v.z),
            d3 = pack2(v.z, v.w), d4 = pack2(v.w, rf);
        const ull* wr = ws + il * 18;

        #pragma unroll
        for (int j = 0; j < 3; ++j) {          // channel pairs (2j, 2j+1)
            ulonglong2 w01a = *(const ulonglong2*)(wr + 4 * j);      // o=2j
            ulonglong2 w01b = *(const ulonglong2*)(wr + 4 * j + 2);  // o=2j+1
            ulonglong2 w2p  = *(const ulonglong2*)(wr + 12 + 2 * j); // W2 pair

            acc[2*j][0]   = fma2(d0, w01a.x, acc[2*j][0]);
            acc[2*j][0]   = fma2(d1, w01a.y, acc[2*j][0]);
            acc[2*j][0]   = fma2(d2, w2p.x,  acc[2*j][0]);
            acc[2*j][1]   = fma2(d2, w01a.x, acc[2*j][1]);
            acc[2*j][1]   = fma2(d3, w01a.y, acc[2*j][1]);
            acc[2*j][1]   = fma2(d4, w2p.x,  acc[2*j][1]);

            acc[2*j+1][0] = fma2(d0, w01b.x, acc[2*j+1][0]);
            acc[2*j+1][0] = fma2(d1, w01b.y, acc[2*j+1][0]);
            acc[2*j+1][0] = fma2(d2, w2p.y,  acc[2*j+1][0]);
            acc[2*j+1][1] = fma2(d2, w01b.x, acc[2*j+1][1]);
            acc[2*j+1][1] = fma2(d3, w01b.y, acc[2*j+1][1]);
            acc[2*j+1][1] = fma2(d4, w2p.y,  acc[2*j+1][1]);
        }
    }

    #pragma unroll
    for (int o = 0; o < 6; ++o) {
        // bias contributed exactly once (the parts are summed in K2)
        float bias = (part == 0) ? ((o < 4) ? rot_b[o] : trans_b[o - 4]) : 0.f;
        float p0, p1, p2, p3;
        unpack2(acc[o][0], p0, p1);
        unpack2(acc[o][1], p2, p3);
        float* dst = g_six + ((size_t)((part * NB + b) * 6 + o)) * NN + n0;
        *(float4*)dst = make_float4(p0 + bias, p1 + bias, p2 + bias, p3 + bias);
    }
}

// ---------------- K2: offsets + pos conv (precontracted) + ratio + BN1 sums --
// grid (16, 32): x = n-tile of 512, y = batch. 256 threads, 2 pts/thread
// (512 blocks -> ~3.5/SM, doubles latency cover vs the 256-block version).
__global__ __launch_bounds__(256) void k2_pos(
    const float* __restrict__ pts,
    const float* __restrict__ pos_w, const float* __restrict__ pos_b)
{
    __shared__ float sc[6][9];   // [c*3+k][ap0,ap1,aa,ab,ac,ad,atx,aty,kappa]
    __shared__ float pw[120];
    __shared__ float pbs[2];
    const int tid = threadIdx.x;

    // fused zero of BN2 accumulators (consumed in k4, after k3's atomics)
    if (blockIdx.x == 0 && blockIdx.y == 0 && tid >= 32 && tid < 36)
        g_bn2[tid - 32] = 0.0;

    if (tid < 120) pw[tid] = pos_w[tid];
    if (tid < 2)   pbs[tid] = pos_b[tid];
    __syncthreads();

    const float R0c[9] = {-1.f,-1.f,-1.f, 0.f,0.f,0.f, 1.f,1.f,1.f};
    const float R1c[9] = {-1.f, 0.f, 1.f,-1.f,0.f,1.f,-1.f,0.f,1.f};

    if (tid < 6) {
        int c = tid / 3, k = tid % 3;
        float aa = 0.f, ab = 0.f, ac = 0.f, ad = 0.f, atx = 0.f, aty = 0.f;
        #pragma unroll
        for (int r = 0; r < 9; ++r) {
            float wox = pw[c * 60 + (2 + 2 * r) * 3 + k];
            float woy = pw[c * 60 + (3 + 2 * r) * 3 + k];
            aa += wox * R0c[r]; ab += wox * R1c[r]; atx += wox;
            ac += woy * R0c[r]; ad += woy * R1c[r]; aty += woy;
        }
        sc[tid][0] = pw[c * 60 + 0 + k];
        sc[tid][1] = pw[c * 60 + 3 + k];
        sc[tid][2] = aa; sc[tid][3] = ab; sc[tid][4] = ac; sc[tid][5] = ad;
        sc[tid][6] = atx; sc[tid][7] = aty;
        sc[tid][8] = -(aa + ad);           // kappa
    }
    __syncthreads();

    const int b  = blockIdx.y;
    const int n0 = blockIdx.x * 512 + tid * 2;
    const bool has_l = (n0 > 0);
    const bool has_r = (n0 + 2 < NN);

    // window positions 0..3 = n0-1 .. n0+2
    float va[4], vb[4], vc[4], vd[4], vtx[4], vty[4], vp0[4], vp1[4];
    {
        #pragma unroll
        for (int ch = 0; ch < 6; ++ch) {
            float l = 0.f, r = 0.f;
            float2 s2 = make_float2(0.f, 0.f);
            #pragma unroll
            for (int p = 0; p < NPART; ++p) {
                const float* s = g_six + ((size_t)((p * NB + b) * 6 + ch)) * NN + n0;
                float2 a = *(const float2*)s;
                s2.x += a.x; s2.y += a.y;
                if (has_l) l += s[-1];
                if (has_r) r += s[2];
            }
            float* dst = (ch == 0) ? va : (ch == 1) ? vb : (ch == 2) ? vc
                       : (ch == 3) ? vd : (ch == 4) ? vtx : vty;
            dst[0] = l; dst[1] = s2.x; dst[2] = s2.y; dst[3] = r;
        }
        const float* p0p = pts + (size_t)(b * 2 + 0) * NN + n0;
        const float* p1p = pts + (size_t)(b * 2 + 1) * NN + n0;
        float2 q0 = *(const float2*)p0p;
        float2 q1 = *(const float2*)p1p;
        vp0[0] = has_l ? p0p[-1] : 0.f;  vp1[0] = has_l ? p1p[-1] : 0.f;
        vp0[3] = has_r ? p0p[2]  : 0.f;  vp1[3] = has_r ? p1p[2]  : 0.f;
        vp0[1] = q0.x; vp0[2] = q0.y;
        vp1[1] = q1.x; vp1[2] = q1.y;
    }

    float x2a[2], x2b[2], rmax[2];
    #pragma unroll
    for (int j = 0; j < 2; ++j) { x2a[j] = pbs[0]; x2b[j] = pbs[1]; }

    #pragma unroll
    for (int t = 0; t < 4; ++t) {
        int nn = n0 - 1 + t;
        if (nn < 0 || nn >= NN) continue;   // zero-padded conv input
        #pragma unroll
        for (int ck = 0; ck < 6; ++ck) {
            float s = sc[ck][8];
            s += sc[ck][0] * vp0[t] + sc[ck][1] * vp1[t];
            s += sc[ck][2] * va[t]  + sc[ck][3] * vb[t];
            s += sc[ck][4] * vc[t]  + sc[ck][5] * vd[t];
            s += sc[ck][6] * vtx[t] + sc[ck][7] * vty[t];
            int c = ck / 3, k = ck % 3;
            int j = t - k;
            if (j >= 0 && j < 2) {
                if (c == 0) x2a[j] += s; else x2b[j] += s;
            }
        }
        // center-tap ratio max (position t serves output j = t-1)
        if (t >= 1 && t <= 2) {
            float rm = -3.4e38f;
            #pragma unroll
            for (int r = 0; r < 9; ++r) {
                float ox = va[t] * R0c[r] + vb[t] * R1c[r] - R0c[r] + vtx[t];
                float oy = vc[t] * R0c[r] + vd[t] * R1c[r] - R1c[r] + vty[t];
                float rr = __fdividef(oy + 1e-6f, ox + 1e-6f);
                rm = fmaxf(rm, rr);
            }
            rmax[t - 1] = rm;
        }
    }

    *(float2*)(g_x2 + (size_t)(b * 2 + 0) * NN + n0) = make_float2(x2a[0], x2a[1]);
    *(float2*)(g_x2 + (size_t)(b * 2 + 1) * NN + n0) = make_float2(x2b[0], x2b[1]);
    *(float2*)(g_r + (size_t)b * NN + n0) = make_float2(rmax[0], rmax[1]);

    float sa  = x2a[0] + x2a[1];
    float sa2 = x2a[0]*x2a[0] + x2a[1]*x2a[1];
    float sb2 = x2b[0] + x2b[1];
    float sbb = x2b[0]*x2b[0] + x2b[1]*x2b[1];
    float s;
    s = brsum(sa);  if (tid == 0) atomicAdd(&g_bn1[0], (double)s);
    s = brsum(sa2); if (tid == 0) atomicAdd(&g_bn1[1], (double)s);
    s = brsum(sb2); if (tid == 0) atomicAdd(&g_bn1[2], (double)s);
    s = brsum(sbb); if (tid == 0) atomicAdd(&g_bn1[3], (double)s);
}

// ---------------- K3: BN1 apply + leaky + rotate + ori conv + BN2 sums -------
// grid (16, 32), 256 threads, 2 pts/thread.
__global__ __launch_bounds__(256) void k3_ori(
    const float* __restrict__ pos_g, const float* __restrict__ pos_beta,
    const float* __restrict__ ori_w, const float* __restrict__ ori_b)
{
    __shared__ float cs[4];
    __shared__ float ow[12];
    const int tid = threadIdx.x;
    if (tid == 0) bn_consts(g_bn1, pos_g, pos_beta, cs);
    if (tid < 12) ow[tid] = ori_w[tid];
    __syncthreads();

    const float sc0 = cs[0], sh0 = cs[1], sc1 = cs[2], sh1 = cs[3];
    const int b  = blockIdx.y;
    const int n0 = blockIdx.x * 512 + tid * 2;
    const bool has_l = (n0 > 0);
    const bool has_r = (n0 + 2 < NN);

    float x0v[4], x1v[4], rv[4];
    {
        const float* q0 = g_x2 + (size_t)(b * 2 + 0) * NN + n0;
        const float* q1 = g_x2 + (size_t)(b * 2 + 1) * NN + n0;
        const float* qr = g_r + (size_t)b * NN + n0;
        float2 a0 = *(const float2*)q0;
        float2 a1 = *(const float2*)q1;
        float2 ar = *(const float2*)qr;
        x0v[0] = has_l ? q0[-1] : 0.f;  x1v[0] = has_l ? q1[-1] : 0.f;
        rv[0]  = has_l ? qr[-1] : 0.f;
        x0v[3] = has_r ? q0[2] : 0.f;   x1v[3] = has_r ? q1[2] : 0.f;
        rv[3]  = has_r ? qr[2] : 0.f;
        x0v[1] = a0.x; x0v[2] = a0.y;
        x1v[1] = a1.x; x1v[2] = a1.y;
        rv[1]  = ar.x; rv[2]  = ar.y;
    }

    float o0[2], o1[2];
    #pragma unroll
    for (int j = 0; j < 2; ++j) { o0[j] = ori_b[0]; o1[j] = ori_b[1]; }

    #pragma unroll
    for (int t = 0; t < 4; ++t) {
        int nn = n0 - 1 + t;
        if (nn < 0 || nn >= NN) continue;   // zero-padded conv input

        float r = fminf(fmaxf(rv[t], -1e18f), 1e18f);
        float xb0 = sc0 * x0v[t] + sh0; xb0 = (xb0 >= 0.f) ? xb0 : 0.2f * xb0;
        float xb1 = sc1 * x1v[t] + sh1; xb1 = (xb1 >= 0.f) ? xb1 : 0.2f * xb1;
        float cc = rsqrtf(fmaf(r, r, 1.f));
        float ss = r * cc;
        float y0 = xb0 * cc - xb1 * ss;
        float y1 = xb0 * ss + xb1 * cc;

        #pragma unroll
        for (int k = 0; k < 3; ++k) {
            int j = t - k;
            if (j >= 0 && j < 2) {
                o0[j] += y0 * ow[0 + k] + y1 * ow[3 + k];
                o1[j] += y0 * ow[6 + k] + y1 * ow[9 + k];
            }
        }
    }

    *(float2*)(g_y3 + (size_t)(b * 2 + 0) * NN + n0) = make_float2(o0[0], o0[1]);
    *(float2*)(g_y3 + (size_t)(b * 2 + 1) * NN + n0) = make_float2(o1[0], o1[1]);

    float s0  = o0[0] + o0[1];
    float s0q = o0[0]*o0[0] + o0[1]*o0[1];
    float s1  = o1[0] + o1[1];
    float s1q = o1[0]*o1[0] + o1[1]*o1[1];
    float s;
    s = brsum(s0);  if (tid == 0) atomicAdd(&g_bn2[0], (double)s);
    s = brsum(s0q); if (tid == 0) atomicAdd(&g_bn2[1], (double)s);
    s = brsum(s1);  if (tid == 0) atomicAdd(&g_bn2[2], (double)s);
    s = brsum(s1q); if (tid == 0) atomicAdd(&g_bn2[3], (double)s);
}

// ---------------- K4: BN2 apply -> output (float2, 1024 blocks) --------------
__global__ __launch_bounds__(256) void k4_out(
    const float* __restrict__ ori_g, const float* __restrict__ ori_beta,
    float* __restrict__ out)
{
    __shared__ float cs[4];
    const int tid = threadIdx.x;
    if (tid == 0) bn_consts(g_bn2, ori_g, ori_beta, cs);
    __syncthreads();

    int idx = (blockIdx.x * 256 + tid) * 2;
    if (idx >= NB * 2 * NN) return;
    int ch = (idx >> 13) & 1;
    float sc = cs[ch * 2], sh = cs[ch * 2 + 1];
    float2 v = *(const float2*)(g_y3 + idx);
    *(float2*)(out + idx) = make_float2(sc * v.x + sh, sc * v.y + sh);
}

// ---------------- launch ------------------------------------------------------
extern "C" void kernel_launch(void* const* d_in, const int* in_sizes, int n_in,
                              void* d_out, int out_size)
{
    const float* pts      = (const float*)d_in[0];
    const float* feats    = (const float*)d_in[1];
    const float* rot_w    = (const float*)d_in[2];
    const float* rot_b    = (const float*)d_in[3];
    const float* trans_w  = (const float*)d_in[4];
    const float* trans_b  = (const float*)d_in[5];
    const float* pos_w    = (const float*)d_in[6];
    const float* pos_b    = (const float*)d_in[7];
    const float* pos_g    = (const float*)d_in[8];
    const float* pos_beta = (const float*)d_in[9];
    const float* ori_w    = (const float*)d_in[10];
    const float* ori_b    = (const float*)d_in[11];
    const float* ori_g    = (const float*)d_in[12];
    const float* ori_beta = (const float*)d_in[13];
    float* out = (float*)d_out;

    k1_conv<<<dim3(16, NPART, 32), 128>>>(feats, rot_w, rot_b, trans_w, trans_b); // 1
    k2_pos<<<dim3(16, 32), 256>>>(pts, pos_w, pos_b);                             // 2
    k3_ori<<<dim3(16, 32), 256>>>(pos_g, pos_beta, ori_w, ori_b);                 // 3
    k4_out<<<1024, 256>>>(ori_g, ori_beta, out);                                  // 4
}

// round 15
// speedup vs baseline: 1.1349x; 1.0618x over previous
#include <cuda_runtime.h>

typedef unsigned long long ull;

#define NB 32
#define ND 256
#define NN 8192
#define NPART 2
#define CHPP (ND / NPART)      // 128 channels per part
#define CNT_PER_CH (NB * NN)   // 262144

// ---------------- scratch (static device globals; no runtime alloc) ----------
__device__ float  g_six[NPART * NB * 6 * NN];  // partials of the 6-ch conv
__device__ float  g_x2 [NB * 2 * NN];
__device__ float  g_r  [NB * NN];
__device__ float  g_y3 [NB * 2 * NN];
__device__ double g_bn1[4];
__device__ double g_bn2[4];

// ---------------- f32x2 helpers ----------------------------------------------
__device__ __forceinline__ ull pack2(float lo, float hi) {
    ull r; asm("mov.b64 %0, {%1,%2};" : "=l"(r) : "f"(lo), "f"(hi)); return r;
}
__device__ __forceinline__ void unpack2(ull v, float& lo, float& hi) {
    asm("mov.b64 {%0,%1}, %2;" : "=f"(lo), "=f"(hi) : "l"(v));
}
__device__ __forceinline__ ull fma2(ull a, ull b, ull c) {
    ull d; asm("fma.rn.f32x2 %0, %1, %2, %3;" : "=l"(d) : "l"(a), "l"(b), "l"(c));
    return d;
}
// streaming (evict-first) loads for read-once data
__device__ __forceinline__ float4 ldcs4(const float* p) {
    float4 v;
    asm("ld.global.cs.v4.f32 {%0,%1,%2,%3}, [%4];"
        : "=f"(v.x), "=f"(v.y), "=f"(v.z), "=f"(v.w) : "l"(p));
    return v;
}
__device__ __forceinline__ float ldcs1(const float* p) {
    float v; asm("ld.global.cs.f32 %0, [%1];" : "=f"(v) : "l"(p)); return v;
}

// ---------------- fast BN constants (fp64 only for mean/var products) --------
__device__ __forceinline__ void bn_consts(const double* acc,
                                          const float* g, const float* beta,
                                          float* cs)
{
    const double ic = 1.0 / (double)CNT_PER_CH;
    double m0d = acc[0] * ic;
    double v0d = acc[1] * ic - m0d * m0d;
    double m1d = acc[2] * ic;
    double v1d = acc[3] * ic - m1d * m1d;
    float v0 = (float)v0d + 1e-5f;
    float v1 = (float)v1d + 1e-5f;
    float m0 = (float)m0d, m1 = (float)m1d;
    float i0 = rsqrtf(v0); i0 *= (1.5f - 0.5f * v0 * i0 * i0);
    float i1 = rsqrtf(v1); i1 *= (1.5f - 0.5f * v1 * i1 * i1);
    float s0 = g[0] * i0, s1 = g[1] * i1;
    cs[0] = s0; cs[1] = beta[0] - m0 * s0;
    cs[2] = s1; cs[3] = beta[1] - m1 * s1;
}

// ---------------- block reduction --------------------------------------------
__device__ __forceinline__ float brsum(float v) {
    __shared__ float sb[8];
    #pragma unroll
    for (int o = 16; o; o >>= 1) v += __shfl_down_sync(0xffffffffu, v, o);
    if ((threadIdx.x & 31) == 0) sb[threadIdx.x >> 5] = v;
    __syncthreads();
    if (threadIdx.x < 32) {
        v = (threadIdx.x < 8) ? sb[threadIdx.x] : 0.f;
        #pragma unroll
        for (int o = 4; o; o >>= 1) v += __shfl_down_sync(0xffffffffu, v, o);
    }
    __syncthreads();
    return v;  // valid on thread 0
}

// ---------------- K1: heavy conv, f32x2 — round-12 config + streaming loads --
// grid (16, 2, 32): x = n-tile of 512, y = channel half, z = batch.
// 128 threads; 4 points/thread; plain in-loop loads + unroll 4 (ptxas batches
// LDGs itself). Halos via SHFL + 1-lane predicated boundary loads.
// (128,8): regs<=64 -> 8 blocks/SM. feats is read-once -> ld.global.cs keeps
// L2 free for the g_six producer->consumer reuse.
__global__ __launch_bounds__(128, 8) void k1_conv(
    const float* __restrict__ feats,
    const float* __restrict__ rot_w,  const float* __restrict__ rot_b,
    const float* __restrict__ trans_w, const float* __restrict__ trans_b)
{
    // per il row of 18 ulls (144B, 16B-aligned):
    //   slots 0..11:  [W0_o, W1_o] pairs for o = 0..5
    //   slots 12..17: [W2_0,W2_1][W2_2,W2_3][W2_4,W2_5]
    __shared__ __align__(16) ull ws[CHPP * 18];
    const int tid  = threadIdx.x;
    const int w    = tid >> 5;
    const int l    = tid & 31;
    const int part = blockIdx.y;
    const int b    = blockIdx.z;

    // fused zero of BN1 accumulators (consumed in k3, after k2's atomics)
    if (blockIdx.x == 0 && part == 0 && b == 0 && tid < 4) g_bn1[tid] = 0.0;

    for (int idx = tid; idx < CHPP * 18; idx += 128) {
        int ich = idx / 18, rem = idx % 18;
        int o, k;
        if (rem < 12) { o = rem >> 1; k = rem & 1; }
        else          { o = rem - 12; k = 2; }
        int i = part * CHPP + ich;
        float wv = (o < 4) ? rot_w[o * 768 + i * 3 + k]
                           : trans_w[(o - 4) * 768 + i * 3 + k];
        ws[idx] = pack2(wv, wv);
    }
    __syncthreads();

    const int warp_n0 = blockIdx.x * 512 + w * 128;   // warp's first point
    const int n0      = warp_n0 + l * 4;
    const float* fbase = feats + ((size_t)(b * ND + part * CHPP)) * NN + n0;
    const bool wl = (warp_n0 > 0);           // warp-left halo exists
    const bool wr_ok = (warp_n0 + 128 < NN); // warp-right halo exists

    ull acc[6][2];
    #pragma unroll
    for (int o = 0; o < 6; ++o) { acc[o][0] = 0ULL; acc[o][1] = 0ULL; }

    #pragma unroll 4
    for (int il = 0; il < CHPP; ++il) {
        const float* fp = fbase + (size_t)il * NN;
        float4 v = ldcs4(fp);

        // halos from neighbor lanes (exact same values as loads would give)
        float lf = __shfl_up_sync(0xffffffffu, v.w, 1);
        float rf = __shfl_down_sync(0xffffffffu, v.x, 1);
        if (l == 0)  lf = wl    ? ldcs1(fp - 1) : 0.f;  // 1-lane predicated LDG
        if (l == 31) rf = wr_ok ? ldcs1(fp + 4) : 0.f;  // 1-lane predicated LDG

        ull d0 = pack2(lf,  v.x), d1 = pack2(v.x, v.y), d2 = pack2(v.y, v.z),
            d3 = pack2(v.z, v.w), d4 = pack2(v.w, rf);
        const ull* wr = ws + il * 18;

        #pragma unroll
        for (int j = 0; j < 3; ++j) {          // channel pairs (2j, 2j+1)
            ulonglong2 w01a = *(const ulonglong2*)(wr + 4 * j);      // o=2j
            ulonglong2 w01b = *(const ulonglong2*)(wr + 4 * j + 2);  // o=2j+1
            ulonglong2 w2p  = *(const ulonglong2*)(wr + 12 + 2 * j); // W2 pair

            acc[2*j][0]   = fma2(d0, w01a.x, acc[2*j][0]);
            acc[2*j][0]   = fma2(d1, w01a.y, acc[2*j][0]);
            acc[2*j][0]   = fma2(d2, w2p.x,  acc[2*j][0]);
            acc[2*j][1]   = fma2(d2, w01a.x, acc[2*j][1]);
            acc[2*j][1]   = fma2(d3, w01a.y, acc[2*j][1]);
            acc[2*j][1]   = fma2(d4, w2p.x,  acc[2*j][1]);

            acc[2*j+1][0] = fma2(d0, w01b.x, acc[2*j+1][0]);
            acc[2*j+1][0] = fma2(d1, w01b.y, acc[2*j+1][0]);
            acc[2*j+1][0] = fma2(d2, w2p.y,  acc[2*j+1][0]);
            acc[2*j+1][1] = fma2(d2, w01b.x, acc[2*j+1][1]);
            acc[2*j+1][1] = fma2(d3, w01b.y, acc[2*j+1][1]);
            acc[2*j+1][1] = fma2(d4, w2p.y,  acc[2*j+1][1]);
        }
    }

    #pragma unroll
    for (int o = 0; o < 6; ++o) {
        // bias contributed exactly once (the parts are summed in K2)
        float bias = (part == 0) ? ((o < 4) ? rot_b[o] : trans_b[o - 4]) : 0.f;
        float p0, p1, p2, p3;
        unpack2(acc[o][0], p0, p1);
        unpack2(acc[o][1], p2, p3);
        float* dst = g_six + ((size_t)((part * NB + b) * 6 + o)) * NN + n0;
        *(float4*)dst = make_float4(p0 + bias, p1 + bias, p2 + bias, p3 + bias);
    }
}

// ---------------- K2: offsets + pos conv (precontracted) + ratio + BN1 sums --
// grid (8, 32): x = n-tile of 1024, y = batch. 256 threads, 4 pts/thread.
// g_six reads are the LAST use -> streaming loads.
__global__ __launch_bounds__(256) void k2_pos(
    const float* __restrict__ pts,
    const float* __restrict__ pos_w, const float* __restrict__ pos_b)
{
    __shared__ float sc[6][9];   // [c*3+k][ap0,ap1,aa,ab,ac,ad,atx,aty,kappa]
    __shared__ float pw[120];
    __shared__ float pbs[2];
    const int tid = threadIdx.x;

    // fused zero of BN2 accumulators (consumed in k4, after k3's atomics)
    if (blockIdx.x == 0 && blockIdx.y == 0 && tid >= 32 && tid < 36)
        g_bn2[tid - 32] = 0.0;

    if (tid < 120) pw[tid] = pos_w[tid];
    if (tid < 2)   pbs[tid] = pos_b[tid];
    __syncthreads();

    const float R0c[9] = {-1.f,-1.f,-1.f, 0.f,0.f,0.f, 1.f,1.f,1.f};
    const float R1c[9] = {-1.f, 0.f, 1.f,-1.f,0.f,1.f,-1.f,0.f,1.f};

    if (tid < 6) {
        int c = tid / 3, k = tid % 3;
        float aa = 0.f, ab = 0.f, ac = 0.f, ad = 0.f, atx = 0.f, aty = 0.f;
        #pragma unroll
        for (int r = 0; r < 9; ++r) {
            float wox = pw[c * 60 + (2 + 2 * r) * 3 + k];
            float woy = pw[c * 60 + (3 + 2 * r) * 3 + k];
            aa += wox * R0c[r]; ab += wox * R1c[r]; atx += wox;
            ac += woy * R0c[r]; ad += woy * R1c[r]; aty += woy;
        }
        sc[tid][0] = pw[c * 60 + 0 + k];
        sc[tid][1] = pw[c * 60 + 3 + k];
        sc[tid][2] = aa; sc[tid][3] = ab; sc[tid][4] = ac; sc[tid][5] = ad;
        sc[tid][6] = atx; sc[tid][7] = aty;
        sc[tid][8] = -(aa + ad);           // kappa
    }
    __syncthreads();

    const int b  = blockIdx.y;
    const int n0 = blockIdx.x * 1024 + tid * 4;
    const bool has_l = (n0 > 0);
    const bool has_r = (n0 + 4 < NN);

    // load 6 summed channels (2 parts) + 2 pts over window 0..5 (= n0-1..n0+4)
    float va[6], vb[6], vc[6], vd[6], vtx[6], vty[6], vp0[6], vp1[6];
    {
        #pragma unroll
        for (int ch = 0; ch < 6; ++ch) {
            float l = 0.f, r = 0.f;
            float4 s4 = make_float4(0.f, 0.f, 0.f, 0.f);
            #pragma unroll
            for (int p = 0; p < NPART; ++p) {
                const float* s = g_six + ((size_t)((p * NB + b) * 6 + ch)) * NN + n0;
                float4 a = ldcs4(s);
                s4.x += a.x; s4.y += a.y; s4.z += a.z; s4.w += a.w;
                if (has_l) l += ldcs1(s - 1);
                if (has_r) r += ldcs1(s + 4);
            }
            float* dst = (ch == 0) ? va : (ch == 1) ? vb : (ch == 2) ? vc
                       : (ch == 3) ? vd : (ch == 4) ? vtx : vty;
            dst[0] = l; dst[1] = s4.x; dst[2] = s4.y;
            dst[3] = s4.z; dst[4] = s4.w; dst[5] = r;
        }
        const float* p0p = pts + (size_t)(b * 2 + 0) * NN + n0;
        const float* p1p = pts + (size_t)(b * 2 + 1) * NN + n0;
        float4 q0 = *(const float4*)p0p;
        float4 q1 = *(const float4*)p1p;
        vp0[0] = has_l ? p0p[-1] : 0.f;  vp1[0] = has_l ? p1p[-1] : 0.f;
        vp0[5] = has_r ? p0p[4]  : 0.f;  vp1[5] = has_r ? p1p[4]  : 0.f;
        vp0[1] = q0.x; vp0[2] = q0.y; vp0[3] = q0.z; vp0[4] = q0.w;
        vp1[1] = q1.x; vp1[2] = q1.y; vp1[3] = q1.z; vp1[4] = q1.w;
    }

    float x2a[4], x2b[4], rmax[4];
    #pragma unroll
    for (int j = 0; j < 4; ++j) { x2a[j] = pbs[0]; x2b[j] = pbs[1]; }

    #pragma unroll
    for (int t = 0; t < 6; ++t) {
        int nn = n0 - 1 + t;
        if (nn < 0 || nn >= NN) continue;   // zero-padded conv input
        #pragma unroll
        for (int ck = 0; ck < 6; ++ck) {
            float s = sc[ck][8];
            s += sc[ck][0] * vp0[t] + sc[ck][1] * vp1[t];
            s += sc[ck][2] * va[t]  + sc[ck][3] * vb[t];
            s += sc[ck][4] * vc[t]  + sc[ck][5] * vd[t];
            s += sc[ck][6] * vtx[t] + sc[ck][7] * vty[t];
            int c = ck / 3, k = ck % 3;
            int j = t - k;
            if (j >= 0 && j < 4) {
                if (c == 0) x2a[j] += s; else x2b[j] += s;
            }
        }
        // center-tap ratio max (position t serves output j = t-1)
        if (t >= 1 && t <= 4) {
            float rm = -3.4e38f;
            #pragma unroll
            for (int r = 0; r < 9; ++r) {
                float ox = va[t] * R0c[r] + vb[t] * R1c[r] - R0c[r] + vtx[t];
                float oy = vc[t] * R0c[r] + vd[t] * R1c[r] - R1c[r] + vty[t];
                float rr = __fdividef(oy + 1e-6f, ox + 1e-6f);
                rm = fmaxf(rm, rr);
            }
            rmax[t - 1] = rm;
        }
    }

    *(float4*)(g_x2 + (size_t)(b * 2 + 0) * NN + n0) = make_float4(x2a[0], x2a[1], x2a[2], x2a[3]);
    *(float4*)(g_x2 + (size_t)(b * 2 + 1) * NN + n0) = make_float4(x2b[0], x2b[1], x2b[2], x2b[3]);
    *(float4*)(g_r + (size_t)b * NN + n0) = make_float4(rmax[0], rmax[1], rmax[2], rmax[3]);

    float sa  = x2a[0] + x2a[1] + x2a[2] + x2a[3];
    float sa2 = x2a[0]*x2a[0] + x2a[1]*x2a[1] + x2a[2]*x2a[2] + x2a[3]*x2a[3];
    float sb2 = x2b[0] + x2b[1] + x2b[2] + x2b[3];
    float sbb = x2b[0]*x2b[0] + x2b[1]*x2b[1] + x2b[2]*x2b[2] + x2b[3]*x2b[3];
    float s;
    s = brsum(sa);  if (tid == 0) atomicAdd(&g_bn1[0], (double)s);
    s = brsum(sa2); if (tid == 0) atomicAdd(&g_bn1[1], (double)s);
    s = brsum(sb2); if (tid == 0) atomicAdd(&g_bn1[2], (double)s);
    s = brsum(sbb); if (tid == 0) atomicAdd(&g_bn1[3], (double)s);
}

// ---------------- K3: BN1 apply + leaky + rotate + ori conv + BN2 sums -------
// grid (8, 32), 256 threads, 4 pts/thread. g_x2/g_r reads are last use.
__global__ __launch_bounds__(256) void k3_ori(
    const float* __restrict__ pos_g, const float* __restrict__ pos_beta,
    const float* __restrict__ ori_w, const float* __restrict__ ori_b)
{
    __shared__ float cs[4];
    __shared__ float ow[12];
    const int tid = threadIdx.x;
    if (tid == 0) bn_consts(g_bn1, pos_g, pos_beta, cs);
    if (tid < 12) ow[tid] = ori_w[tid];
    __syncthreads();

    const float sc0 = cs[0], sh0 = cs[1], sc1 = cs[2], sh1 = cs[3];
    const int b  = blockIdx.y;
    const int n0 = blockIdx.x * 1024 + tid * 4;
    const bool has_l = (n0 > 0);
    const bool has_r = (n0 + 4 < NN);

    float x0v[6], x1v[6], rv[6];
    {
        const float* q0 = g_x2 + (size_t)(b * 2 + 0) * NN + n0;
        const float* q1 = g_x2 + (size_t)(b * 2 + 1) * NN + n0;
        const float* qr = g_r + (size_t)b * NN + n0;
        float4 a0 = ldcs4(q0);
        float4 a1 = ldcs4(q1);
        float4 ar = ldcs4(qr);
        x0v[0] = has_l ? ldcs1(q0 - 1) : 0.f;  x1v[0] = has_l ? ldcs1(q1 - 1) : 0.f;
        rv[0]  = has_l ? ldcs1(qr - 1) : 0.f;
        x0v[5] = has_r ? ldcs1(q0 + 4) : 0.f;  x1v[5] = has_r ? ldcs1(q1 + 4) : 0.f;
        rv[5]  = has_r ? ldcs1(qr + 4) : 0.f;
        x0v[1] = a0.x; x0v[2] = a0.y; x0v[3] = a0.z; x0v[4] = a0.w;
        x1v[1] = a1.x; x1v[2] = a1.y; x1v[3] = a1.z; x1v[4] = a1.w;
        rv[1]  = ar.x; rv[2]  = ar.y; rv[3]  = ar.z; rv[4]  = ar.w;
    }

    float o0[4], o1[4];
    #pragma unroll
    for (int j = 0; j < 4; ++j) { o0[j] = ori_b[0]; o1[j] = ori_b[1]; }

    #pragma unroll
    for (int t = 0; t < 6; ++t) {
        int nn = n0 - 1 + t;
        if (nn < 0 || nn >= NN) continue;   // zero-padded conv input

        float r = fminf(fmaxf(rv[t], -1e18f), 1e18f);
        float xb0 = sc0 * x0v[t] + sh0; xb0 = (xb0 >= 0.f) ? xb0 : 0.2f * xb0;
        float xb1 = sc1 * x1v[t] + sh1; xb1 = (xb1 >= 0.f) ? xb1 : 0.2f * xb1;
        float cc = rsqrtf(fmaf(r, r, 1.f));
        float ss = r * cc;
        float y0 = xb0 * cc - xb1 * ss;
        float y1 = xb0 * ss + xb1 * cc;

        #pragma unroll
        for (int k = 0; k < 3; ++k) {
            int j = t - k;
            if (j >= 0 && j < 4) {
                o0[j] += y0 * ow[0 + k] + y1 * ow[3 + k];
                o1[j] += y0 * ow[6 + k] + y1 * ow[9 + k];
            }
        }
    }

    *(float4*)(g_y3 + (size_t)(b * 2 + 0) * NN + n0) = make_float4(o0[0], o0[1], o0[2], o0[3]);
    *(float4*)(g_y3 + (size_t)(b * 2 + 1) * NN + n0) = make_float4(o1[0], o1[1], o1[2], o1[3]);

    float s0  = o0[0] + o0[1] + o0[2] + o0[3];
    float s0q = o0[0]*o0[0] + o0[1]*o0[1] + o0[2]*o0[2] + o0[3]*o0[3];
    float s1  = o1[0] + o1[1] + o1[2] + o1[3];
    float s1q = o1[0]*o1[0] + o1[1]*o1[1] + o1[2]*o1[2] + o1[3]*o1[3];
    float s;
    s = brsum(s0);  if (tid == 0) atomicAdd(&g_bn2[0], (double)s);
    s = brsum(s0q); if (tid == 0) atomicAdd(&g_bn2[1], (double)s);
    s = brsum(s1);  if (tid == 0) atomicAdd(&g_bn2[2], (double)s);
    s = brsum(s1q); if (tid == 0) atomicAdd(&g_bn2[3], (double)s);
}

// ---------------- K4: BN2 apply -> output (float2, 1024 blocks) --------------
__global__ __launch_bounds__(256) void k4_out(
    const float* __restrict__ ori_g, const float* __restrict__ ori_beta,
    float* __restrict__ out)
{
    __shared__ float cs[4];
    const int tid = threadIdx.x;
    if (tid == 0) bn_consts(g_bn2, ori_g, ori_beta, cs);
    __syncthreads();

    int idx = (blockIdx.x * 256 + tid) * 2;
    if (idx >= NB * 2 * NN) return;
    int ch = (idx >> 13) & 1;
    float sc = cs[ch * 2], sh = cs[ch * 2 + 1];
    float2 v;
    asm("ld.global.cs.v2.f32 {%0,%1}, [%2];"
        : "=f"(v.x), "=f"(v.y) : "l"(g_y3 + idx));
    *(float2*)(out + idx) = make_float2(sc * v.x + sh, sc * v.y + sh);
}

// ---------------- launch ------------------------------------------------------
extern "C" void kernel_launch(void* const* d_in, const int* in_sizes, int n_in,
                              void* d_out, int out_size)
{
    const float* pts      = (const float*)d_in[0];
    const float* feats    = (const float*)d_in[1];
    const float* rot_w    = (const float*)d_in[2];
    const float* rot_b    = (const float*)d_in[3];
    const float* trans_w  = (const float*)d_in[4];
    const float* trans_b  = (const float*)d_in[5];
    const float* pos_w    = (const float*)d_in[6];
    const float* pos_b    = (const float*)d_in[7];
    const float* pos_g    = (const float*)d_in[8];
    const float* pos_beta = (const float*)d_in[9];
    const float* ori_w    = (const float*)d_in[10];
    const float* ori_b    = (const float*)d_in[11];
    const float* ori_g    = (const float*)d_in[12];
    const float* ori_beta = (const float*)d_in[13];
    float* out = (float*)d_out;

    k1_conv<<<dim3(16, NPART, 32), 128>>>(feats, rot_w, rot_b, trans_w, trans_b); // 1
    k2_pos<<<dim3(8, 32), 256>>>(pts, pos_w, pos_b);                              // 2
    k3_ori<<<dim3(8, 32), 256>>>(pos_g, pos_beta, ori_w, ori_b);                  // 3
    k4_out<<<1024, 256>>>(ori_g, ori_beta, out);                                  // 4
}

// round 16
// speedup vs baseline: 1.1447x; 1.0087x over previous
#include <cuda_runtime.h>

typedef unsigned long long ull;

#define NB 32
#define ND 256
#define NN 8192
#define NPART 2
#define CHPP (ND / NPART)      // 128 channels per part
#define CNT_PER_CH (NB * NN)   // 262144

// ---------------- scratch (static device globals; no runtime alloc) ----------
__device__ float  g_six[NPART * NB * 6 * NN];  // partials of the 6-ch conv
__device__ float  g_x2 [NB * 2 * NN];
__device__ float  g_r  [NB * NN];
__device__ float  g_y3 [NB * 2 * NN];
__device__ double g_bn1[4];
__device__ double g_bn2[4];

// ---------------- f32x2 helpers ----------------------------------------------
__device__ __forceinline__ ull pack2(float lo, float hi) {
    ull r; asm("mov.b64 %0, {%1,%2};" : "=l"(r) : "f"(lo), "f"(hi)); return r;
}
__device__ __forceinline__ void unpack2(ull v, float& lo, float& hi) {
    asm("mov.b64 {%0,%1}, %2;" : "=f"(lo), "=f"(hi) : "l"(v));
}
__device__ __forceinline__ ull fma2(ull a, ull b, ull c) {
    ull d; asm("fma.rn.f32x2 %0, %1, %2, %3;" : "=l"(d) : "l"(a), "l"(b), "l"(c));
    return d;
}
// streaming (evict-first) loads for read-once data
__device__ __forceinline__ float4 ldcs4(const float* p) {
    float4 v;
    asm("ld.global.cs.v4.f32 {%0,%1,%2,%3}, [%4];"
        : "=f"(v.x), "=f"(v.y), "=f"(v.z), "=f"(v.w) : "l"(p));
    return v;
}
__device__ __forceinline__ float ldcs1(const float* p) {
    float v; asm("ld.global.cs.f32 %0, [%1];" : "=f"(v) : "l"(p)); return v;
}

// ---------------- fast BN constants (fp64 only for mean/var products) --------
__device__ __forceinline__ void bn_consts(const double* acc,
                                          const float* g, const float* beta,
                                          float* cs)
{
    const double ic = 1.0 / (double)CNT_PER_CH;
    double m0d = acc[0] * ic;
    double v0d = acc[1] * ic - m0d * m0d;
    double m1d = acc[2] * ic;
    double v1d = acc[3] * ic - m1d * m1d;
    float v0 = (float)v0d + 1e-5f;
    float v1 = (float)v1d + 1e-5f;
    float m0 = (float)m0d, m1 = (float)m1d;
    float i0 = rsqrtf(v0); i0 *= (1.5f - 0.5f * v0 * i0 * i0);
    float i1 = rsqrtf(v1); i1 *= (1.5f - 0.5f * v1 * i1 * i1);
    float s0 = g[0] * i0, s1 = g[1] * i1;
    cs[0] = s0; cs[1] = beta[0] - m0 * s0;
    cs[2] = s1; cs[3] = beta[1] - m1 * s1;
}

// ---------------- block reduction --------------------------------------------
__device__ __forceinline__ float brsum(float v) {
    __shared__ float sb[8];
    #pragma unroll
    for (int o = 16; o; o >>= 1) v += __shfl_down_sync(0xffffffffu, v, o);
    if ((threadIdx.x & 31) == 0) sb[threadIdx.x >> 5] = v;
    __syncthreads();
    if (threadIdx.x < 32) {
        v = (threadIdx.x < 8) ? sb[threadIdx.x] : 0.f;
        #pragma unroll
        for (int o = 4; o; o >>= 1) v += __shfl_down_sync(0xffffffffu, v, o);
    }
    __syncthreads();
    return v;  // valid on thread 0
}

// ---------------- K1: heavy conv, f32x2 — best config + coalesced preload ----
// grid (16, 2, 32): x = n-tile of 512, y = channel half, z = batch.
// 128 threads; 4 points/thread; plain in-loop ldcs + unroll 4; halos via SHFL
// + 1-lane predicated boundary loads. (128,8): regs<=64 -> 32 warps/SM.
// Weight preload walks rot_w/trans_w CONTIGUOUSLY (was stride-3).
__global__ __launch_bounds__(128, 8) void k1_conv(
    const float* __restrict__ feats,
    const float* __restrict__ rot_w,  const float* __restrict__ rot_b,
    const float* __restrict__ trans_w, const float* __restrict__ trans_b)
{
    // per il row of 18 ulls (144B, 16B-aligned):
    //   slots 0..11:  [W0_o, W1_o] pairs for o = 0..5
    //   slots 12..17: [W2_0,W2_1][W2_2,W2_3][W2_4,W2_5]
    __shared__ __align__(16) ull ws[CHPP * 18];
    const int tid  = threadIdx.x;
    const int w    = tid >> 5;
    const int l    = tid & 31;
    const int part = blockIdx.y;
    const int b    = blockIdx.z;

    // fused zero of BN1 accumulators (consumed in k3, after k2's atomics)
    if (blockIdx.x == 0 && part == 0 && b == 0 && tid < 4) g_bn1[tid] = 0.0;

    // coalesced weight preload: j walks the part's contiguous 384-float chunk
    // of each output channel o; slot computed from (ich = j/3, k = j%3).
    for (int idx = tid; idx < 6 * CHPP * 3; idx += 128) {
        int o = idx / (CHPP * 3);          // output channel 0..5
        int j = idx - o * (CHPP * 3);      // 0..383 contiguous within channel
        float wv = (o < 4) ? rot_w[o * 768 + part * (CHPP * 3) + j]
                           : trans_w[(o - 4) * 768 + part * (CHPP * 3) + j];
        int ich = j / 3, k = j - ich * 3;
        int slot = (k < 2) ? (o * 2 + k) : (12 + o);
        ws[ich * 18 + slot] = pack2(wv, wv);
    }
    __syncthreads();

    const int warp_n0 = blockIdx.x * 512 + w * 128;   // warp's first point
    const int n0      = warp_n0 + l * 4;
    const float* fbase = feats + ((size_t)(b * ND + part * CHPP)) * NN + n0;
    const bool wl = (warp_n0 > 0);           // warp-left halo exists
    const bool wr_ok = (warp_n0 + 128 < NN); // warp-right halo exists

    ull acc[6][2];
    #pragma unroll
    for (int o = 0; o < 6; ++o) { acc[o][0] = 0ULL; acc[o][1] = 0ULL; }

    #pragma unroll 4
    for (int il = 0; il < CHPP; ++il) {
        const float* fp = fbase + (size_t)il * NN;
        float4 v = ldcs4(fp);

        // halos from neighbor lanes (exact same values as loads would give)
        float lf = __shfl_up_sync(0xffffffffu, v.w, 1);
        float rf = __shfl_down_sync(0xffffffffu, v.x, 1);
        if (l == 0)  lf = wl    ? ldcs1(fp - 1) : 0.f;  // 1-lane predicated LDG
        if (l == 31) rf = wr_ok ? ldcs1(fp + 4) : 0.f;  // 1-lane predicated LDG

        ull d0 = pack2(lf,  v.x), d1 = pack2(v.x, v.y), d2 = pack2(v.y, v.z),
            d3 = pack2(v.z, v.w), d4 = pack2(v.w, rf);
        const ull* wr = ws + il * 18;

        #pragma unroll
        for (int j = 0; j < 3; ++j) {          // channel pairs (2j, 2j+1)
            ulonglong2 w01a = *(const ulonglong2*)(wr + 4 * j);      // o=2j
            ulonglong2 w01b = *(const ulonglong2*)(wr + 4 * j + 2);  // o=2j+1
            ulonglong2 w2p  = *(const ulonglong2*)(wr + 12 + 2 * j); // W2 pair

            acc[2*j][0]   = fma2(d0, w01a.x, acc[2*j][0]);
            acc[2*j][0]   = fma2(d1, w01a.y, acc[2*j][0]);
            acc[2*j][0]   = fma2(d2, w2p.x,  acc[2*j][0]);
            acc[2*j][1]   = fma2(d2, w01a.x, acc[2*j][1]);
            acc[2*j][1]   = fma2(d3, w01a.y, acc[2*j][1]);
            acc[2*j][1]   = fma2(d4, w2p.x,  acc[2*j][1]);

            acc[2*j+1][0] = fma2(d0, w01b.x, acc[2*j+1][0]);
            acc[2*j+1][0] = fma2(d1, w01b.y, acc[2*j+1][0]);
            acc[2*j+1][0] = fma2(d2, w2p.y,  acc[2*j+1][0]);
            acc[2*j+1][1] = fma2(d2, w01b.x, acc[2*j+1][1]);
            acc[2*j+1][1] = fma2(d3, w01b.y, acc[2*j+1][1]);
            acc[2*j+1][1] = fma2(d4, w2p.y,  acc[2*j+1][1]);
        }
    }

    #pragma unroll
    for (int o = 0; o < 6; ++o) {
        // bias contributed exactly once (the parts are summed in K2)
        float bias = (part == 0) ? ((o < 4) ? rot_b[o] : trans_b[o - 4]) : 0.f;
        float p0, p1, p2, p3;
        unpack2(acc[o][0], p0, p1);
        unpack2(acc[o][1], p2, p3);
        float* dst = g_six + ((size_t)((part * NB + b) * 6 + o)) * NN + n0;
        *(float4*)dst = make_float4(p0 + bias, p1 + bias, p2 + bias, p3 + bias);
    }
}

// ---------------- K2: offsets + pos conv (precontracted) + ratio + BN1 sums --
// grid (8, 32): x = n-tile of 1024, y = batch. 256 threads, 4 pts/thread.
// g_six reads are the LAST use -> streaming loads.
__global__ __launch_bounds__(256) void k2_pos(
    const float* __restrict__ pts,
    const float* __restrict__ pos_w, const float* __restrict__ pos_b)
{
    __shared__ float sc[6][9];   // [c*3+k][ap0,ap1,aa,ab,ac,ad,atx,aty,kappa]
    __shared__ float pw[120];
    __shared__ float pbs[2];
    const int tid = threadIdx.x;

    // fused zero of BN2 accumulators (consumed in k4, after k3's atomics)
    if (blockIdx.x == 0 && blockIdx.y == 0 && tid >= 32 && tid < 36)
        g_bn2[tid - 32] = 0.0;

    if (tid < 120) pw[tid] = pos_w[tid];
    if (tid < 2)   pbs[tid] = pos_b[tid];
    __syncthreads();

    const float R0c[9] = {-1.f,-1.f,-1.f, 0.f,0.f,0.f, 1.f,1.f,1.f};
    const float R1c[9] = {-1.f, 0.f, 1.f,-1.f,0.f,1.f,-1.f,0.f,1.f};

    if (tid < 6) {
        int c = tid / 3, k = tid % 3;
        float aa = 0.f, ab = 0.f, ac = 0.f, ad = 0.f, atx = 0.f, aty = 0.f;
        #pragma unroll
        for (int r = 0; r < 9; ++r) {
            float wox = pw[c * 60 + (2 + 2 * r) * 3 + k];
            float woy = pw[c * 60 + (3 + 2 * r) * 3 + k];
            aa += wox * R0c[r]; ab += wox * R1c[r]; atx += wox;
            ac += woy * R0c[r]; ad += woy * R1c[r]; aty += woy;
        }
        sc[tid][0] = pw[c * 60 + 0 + k];
        sc[tid][1] = pw[c * 60 + 3 + k];
        sc[tid][2] = aa; sc[tid][3] = ab; sc[tid][4] = ac; sc[tid][5] = ad;
        sc[tid][6] = atx; sc[tid][7] = aty;
        sc[tid][8] = -(aa + ad);           // kappa
    }
    __syncthreads();

    const int b  = blockIdx.y;
    const int n0 = blockIdx.x * 1024 + tid * 4;
    const bool has_l = (n0 > 0);
    const bool has_r = (n0 + 4 < NN);

    // load 6 summed channels (2 parts) + 2 pts over window 0..5 (= n0-1..n0+4)
    float va[6], vb[6], vc[6], vd[6], vtx[6], vty[6], vp0[6], vp1[6];
    {
        #pragma unroll
        for (int ch = 0; ch < 6; ++ch) {
            float l = 0.f, r = 0.f;
            float4 s4 = make_float4(0.f, 0.f, 0.f, 0.f);
            #pragma unroll
            for (int p = 0; p < NPART; ++p) {
                const float* s = g_six + ((size_t)((p * NB + b) * 6 + ch)) * NN + n0;
                float4 a = ldcs4(s);
                s4.x += a.x; s4.y += a.y; s4.z += a.z; s4.w += a.w;
                if (has_l) l += ldcs1(s - 1);
                if (has_r) r += ldcs1(s + 4);
            }
            float* dst = (ch == 0) ? va : (ch == 1) ? vb : (ch == 2) ? vc
                       : (ch == 3) ? vd : (ch == 4) ? vtx : vty;
            dst[0] = l; dst[1] = s4.x; dst[2] = s4.y;
            dst[3] = s4.z; dst[4] = s4.w; dst[5] = r;
        }
        const float* p0p = pts + (size_t)(b * 2 + 0) * NN + n0;
        const float* p1p = pts + (size_t)(b * 2 + 1) * NN + n0;
        float4 q0 = *(const float4*)p0p;
        float4 q1 = *(const float4*)p1p;
        vp0[0] = has_l ? p0p[-1] : 0.f;  vp1[0] = has_l ? p1p[-1] : 0.f;
        vp0[5] = has_r ? p0p[4]  : 0.f;  vp1[5] = has_r ? p1p[4]  : 0.f;
        vp0[1] = q0.x; vp0[2] = q0.y; vp0[3] = q0.z; vp0[4] = q0.w;
        vp1[1] = q1.x; vp1[2] = q1.y; vp1[3] = q1.z; vp1[4] = q1.w;
    }

    float x2a[4], x2b[4], rmax[4];
    #pragma unroll
    for (int j = 0; j < 4; ++j) { x2a[j] = pbs[0]; x2b[j] = pbs[1]; }

    #pragma unroll
    for (int t = 0; t < 6; ++t) {
        int nn = n0 - 1 + t;
        if (nn < 0 || nn >= NN) continue;   // zero-padded conv input
        #pragma unroll
        for (int ck = 0; ck < 6; ++ck) {
            float s = sc[ck][8];
            s += sc[ck][0] * vp0[t] + sc[ck][1] * vp1[t];
            s += sc[ck][2] * va[t]  + sc[ck][3] * vb[t];
            s += sc[ck][4] * vc[t]  + sc[ck][5] * vd[t];
            s += sc[ck][6] * vtx[t] + sc[ck][7] * vty[t];
            int c = ck / 3, k = ck % 3;
            int j = t - k;
            if (j >= 0 && j < 4) {
                if (c == 0) x2a[j] += s; else x2b[j] += s;
            }
        }
        // center-tap ratio max (position t serves output j = t-1)
        if (t >= 1 && t <= 4) {
            float rm = -3.4e38f;
            #pragma unroll
            for (int r = 0; r < 9; ++r) {
                float ox = va[t] * R0c[r] + vb[t] * R1c[r] - R0c[r] + vtx[t];
                float oy = vc[t] * R0c[r] + vd[t] * R1c[r] - R1c[r] + vty[t];
                float rr = __fdividef(oy + 1e-6f, ox + 1e-6f);
                rm = fmaxf(rm, rr);
            }
            rmax[t - 1] = rm;
        }
    }

    *(float4*)(g_x2 + (size_t)(b * 2 + 0) * NN + n0) = make_float4(x2a[0], x2a[1], x2a[2], x2a[3]);
    *(float4*)(g_x2 + (size_t)(b * 2 + 1) * NN + n0) = make_float4(x2b[0], x2b[1], x2b[2], x2b[3]);
    *(float4*)(g_r + (size_t)b * NN + n0) = make_float4(rmax[0], rmax[1], rmax[2], rmax[3]);

    float sa  = x2a[0] + x2a[1] + x2a[2] + x2a[3];
    float sa2 = x2a[0]*x2a[0] + x2a[1]*x2a[1] + x2a[2]*x2a[2] + x2a[3]*x2a[3];
    float sb2 = x2b[0] + x2b[1] + x2b[2] + x2b[3];
    float sbb = x2b[0]*x2b[0] + x2b[1]*x2b[1] + x2b[2]*x2b[2] + x2b[3]*x2b[3];
    float s;
    s = brsum(sa);  if (tid == 0) atomicAdd(&g_bn1[0], (double)s);
    s = brsum(sa2); if (tid == 0) atomicAdd(&g_bn1[1], (double)s);
    s = brsum(sb2); if (tid == 0) atomicAdd(&g_bn1[2], (double)s);
    s = brsum(sbb); if (tid == 0) atomicAdd(&g_bn1[3], (double)s);
}

// ---------------- K3: BN1 apply + leaky + rotate + ori conv + BN2 sums -------
// grid (8, 32), 256 threads, 4 pts/thread. g_x2/g_r reads are last use.
__global__ __launch_bounds__(256) void k3_ori(
    const float* __restrict__ pos_g, const float* __restrict__ pos_beta,
    const float* __restrict__ ori_w, const float* __restrict__ ori_b)
{
    __shared__ float cs[4];
    __shared__ float ow[12];
    const int tid = threadIdx.x;
    if (tid == 0) bn_consts(g_bn1, pos_g, pos_beta, cs);
    if (tid < 12) ow[tid] = ori_w[tid];
    __syncthreads();

    const float sc0 = cs[0], sh0 = cs[1], sc1 = cs[2], sh1 = cs[3];
    const int b  = blockIdx.y;
    const int n0 = blockIdx.x * 1024 + tid * 4;
    const bool has_l = (n0 > 0);
    const bool has_r = (n0 + 4 < NN);

    float x0v[6], x1v[6], rv[6];
    {
        const float* q0 = g_x2 + (size_t)(b * 2 + 0) * NN + n0;
        const float* q1 = g_x2 + (size_t)(b * 2 + 1) * NN + n0;
        const float* qr = g_r + (size_t)b * NN + n0;
        float4 a0 = ldcs4(q0);
        float4 a1 = ldcs4(q1);
        float4 ar = ldcs4(qr);
        x0v[0] = has_l ? ldcs1(q0 - 1) : 0.f;  x1v[0] = has_l ? ldcs1(q1 - 1) : 0.f;
        rv[0]  = has_l ? ldcs1(qr - 1) : 0.f;
        x0v[5] = has_r ? ldcs1(q0 + 4) : 0.f;  x1v[5] = has_r ? ldcs1(q1 + 4) : 0.f;
        rv[5]  = has_r ? ldcs1(qr + 4) : 0.f;
        x0v[1] = a0.x; x0v[2] = a0.y; x0v[3] = a0.z; x0v[4] = a0.w;
        x1v[1] = a1.x; x1v[2] = a1.y; x1v[3] = a1.z; x1v[4] = a1.w;
        rv[1]  = ar.x; rv[2]  = ar.y; rv[3]  = ar.z; rv[4]  = ar.w;
    }

    float o0[4], o1[4];
    #pragma unroll
    for (int j = 0; j < 4; ++j) { o0[j] = ori_b[0]; o1[j] = ori_b[1]; }

    #pragma unroll
    for (int t = 0; t < 6; ++t) {
        int nn = n0 - 1 + t;
        if (nn < 0 || nn >= NN) continue;   // zero-padded conv input

        float r = fminf(fmaxf(rv[t], -1e18f), 1e18f);
        float xb0 = sc0 * x0v[t] + sh0; xb0 = (xb0 >= 0.f) ? xb0 : 0.2f * xb0;
        float xb1 = sc1 * x1v[t] + sh1; xb1 = (xb1 >= 0.f) ? xb1 : 0.2f * xb1;
        float cc = rsqrtf(fmaf(r, r, 1.f));
        float ss = r * cc;
        float y0 = xb0 * cc - xb1 * ss;
        float y1 = xb0 * ss + xb1 * cc;

        #pragma unroll
        for (int k = 0; k < 3; ++k) {
            int j = t - k;
            if (j >= 0 && j < 4) {
                o0[j] += y0 * ow[0 + k] + y1 * ow[3 + k];
                o1[j] += y0 * ow[6 + k] + y1 * ow[9 + k];
            }
        }
    }

    *(float4*)(g_y3 + (size_t)(b * 2 + 0) * NN + n0) = make_float4(o0[0], o0[1], o0[2], o0[3]);
    *(float4*)(g_y3 + (size_t)(b * 2 + 1) * NN + n0) = make_float4(o1[0], o1[1], o1[2], o1[3]);

    float s0  = o0[0] + o0[1] + o0[2] + o0[3];
    float s0q = o0[0]*o0[0] + o0[1]*o0[1] + o0[2]*o0[2] + o0[3]*o0[3];
    float s1  = o1[0] + o1[1] + o1[2] + o1[3];
    float s1q = o1[0]*o1[0] + o1[1]*o1[1] + o1[2]*o1[2] + o1[3]*o1[3];
    float s;
    s = brsum(s0);  if (tid == 0) atomicAdd(&g_bn2[0], (double)s);
    s = brsum(s0q); if (tid == 0) atomicAdd(&g_bn2[1], (double)s);
    s = brsum(s1);  if (tid == 0) atomicAdd(&g_bn2[2], (double)s);
    s = brsum(s1q); if (tid == 0) atomicAdd(&g_bn2[3], (double)s);
}

// ---------------- K4: BN2 apply -> output (float2, 1024 blocks) --------------
__global__ __launch_bounds__(256) void k4_out(
    const float* __restrict__ ori_g, const float* __restrict__ ori_beta,
    float* __restrict__ out)
{
    __shared__ float cs[4];
    const int tid = threadIdx.x;
    if (tid == 0) bn_consts(g_bn2, ori_g, ori_beta, cs);
    __syncthreads();

    int idx = (blockIdx.x * 256 + tid) * 2;
    if (idx >= NB * 2 * NN) return;
    int ch = (idx >> 13) & 1;
    float sc = cs[ch * 2], sh = cs[ch * 2 + 1];
    float2 v;
    asm("ld.global.cs.v2.f32 {%0,%1}, [%2];"
        : "=f"(v.x), "=f"(v.y) : "l"(g_y3 + idx));
    *(float2*)(out + idx) = make_float2(sc * v.x + sh, sc * v.y + sh);
}

// ---------------- launch ------------------------------------------------------
extern "C" void kernel_launch(void* const* d_in, const int* in_sizes, int n_in,
                              void* d_out, int out_size)
{
    const float* pts      = (const float*)d_in[0];
    const float* feats    = (const float*)d_in[1];
    const float* rot_w    = (const float*)d_in[2];
    const float* rot_b    = (const float*)d_in[3];
    const float* trans_w  = (const float*)d_in[4];
    const float* trans_b  = (const float*)d_in[5];
    const float* pos_w    = (const float*)d_in[6];
    const float* pos_b    = (const float*)d_in[7];
    const float* pos_g    = (const float*)d_in[8];
    const float* pos_beta = (const float*)d_in[9];
    const float* ori_w    = (const float*)d_in[10];
    const float* ori_b    = (const float*)d_in[11];
    const float* ori_g    = (const float*)d_in[12];
    const float* ori_beta = (const float*)d_in[13];
    float* out = (float*)d_out;

    k1_conv<<<dim3(16, NPART, 32), 128>>>(feats, rot_w, rot_b, trans_w, trans_b); // 1
    k2_pos<<<dim3(8, 32), 256>>>(pts, pos_w, pos_b);                              // 2
    k3_ori<<<dim3(8, 32), 256>>>(pos_g, pos_beta, ori_w, ori_b);                  // 3
    k4_out<<<1024, 256>>>(ori_g, ori_beta, out);                                  // 4
}